// round 1
// baseline (speedup 1.0000x reference)
#include <cuda_runtime.h>
#include <math.h>

// Problem constants
#define Bb 16
#define Nn 512
#define Hh 768
#define Gg 8
#define Dd 96
#define Ll 16
#define LDIM 1536

// Scratch (device globals -- allocation-free rule)
__device__ float g_Q[(size_t)Bb * Gg * Nn * Dd];          // [b][g][n][d]
__device__ float g_K[(size_t)Bb * Gg * Nn * Dd];          // [b][g][m][d]
__device__ float g_V[(size_t)Bb * Ll * Nn * Dd];          // [b][l][m][d]
__device__ float g_S[(size_t)Bb * Gg * Nn * Nn];          // [b][g][n][m]
__device__ float g_A[(size_t)Bb * Ll * Nn * Nn];          // [b][l][n][m]
__device__ float g_O[(size_t)Bb * Nn * LDIM];             // [b][n][l*d]

// ---------------------------------------------------------------------------
// K1/K5: C = X(MxK) @ W(KxN) [+bias].  headCount>0 => permuted store into
// [b][head][n][96] layout; headCount==0 => plain row-major store.
// Classic 128x128x8 register-blocked SGEMM, 256 threads, 8x8 microtile.
// Requires M%128==0, N%128==0, K%8==0 (true for all our shapes).
// ---------------------------------------------------------------------------
__global__ void __launch_bounds__(256) sgemm_kernel(
    const float* __restrict__ X, const float* __restrict__ W,
    const float* __restrict__ bias, float* __restrict__ out,
    int M, int K, int N, int headCount)
{
    __shared__ float As[8][129];   // padded: transposed A tile
    __shared__ float Bs[8][128];

    int tid = threadIdx.x;
    int bx = blockIdx.x, by = blockIdx.y;
    int tx = tid & 15, ty = tid >> 4;

    float acc[8][8];
#pragma unroll
    for (int i = 0; i < 8; i++)
#pragma unroll
        for (int j = 0; j < 8; j++) acc[i][j] = 0.f;

    int aRow = tid >> 1;            // 0..127
    int aCol = (tid & 1) * 4;       // 0 or 4
    int bRow = tid >> 5;            // 0..7
    int bCol = (tid & 31) * 4;      // 0..124

    const float* Ablk = X + (size_t)(by * 128) * K;
    const float* Bblk = W + bx * 128;

    for (int k0 = 0; k0 < K; k0 += 8) {
        float4 av = *(const float4*)(Ablk + (size_t)aRow * K + k0 + aCol);
        As[aCol + 0][aRow] = av.x;
        As[aCol + 1][aRow] = av.y;
        As[aCol + 2][aRow] = av.z;
        As[aCol + 3][aRow] = av.w;
        float4 bv = *(const float4*)(Bblk + (size_t)(k0 + bRow) * N + bCol);
        *(float4*)&Bs[bRow][bCol] = bv;
        __syncthreads();
#pragma unroll
        for (int kk = 0; kk < 8; kk++) {
            float ar[8], br[8];
#pragma unroll
            for (int i = 0; i < 8; i++) ar[i] = As[kk][ty + i * 16];
#pragma unroll
            for (int j = 0; j < 8; j++) br[j] = Bs[kk][tx + j * 16];
#pragma unroll
            for (int i = 0; i < 8; i++)
#pragma unroll
                for (int j = 0; j < 8; j++)
                    acc[i][j] = fmaf(ar[i], br[j], acc[i][j]);
        }
        __syncthreads();
    }

#pragma unroll
    for (int i = 0; i < 8; i++) {
        int row = by * 128 + ty + i * 16;
        int b = row >> 9, n = row & 511;
#pragma unroll
        for (int j = 0; j < 8; j++) {
            int col = bx * 128 + tx + j * 16;
            float v = acc[i][j];
            if (bias) v += bias[col];
            if (headCount) {
                int h = col / 96;
                int d = col - h * 96;
                out[(((size_t)(b * headCount + h)) * 512 + n) * 96 + d] = v;
            } else {
                out[(size_t)row * N + col] = v;
            }
        }
    }
}

// ---------------------------------------------------------------------------
// K2: S[b,g,n,m] = sum_d Q[b,g,n,d]*K[b,g,m,d] + sigma[g]^2 * eps[b,g,n,m]
// 64x64 tile, K-dim (d)=96 in 3 chunks of 32. 256 threads, 4x4 microtile.
// ---------------------------------------------------------------------------
__global__ void __launch_bounds__(256) scores_kernel(
    const float* __restrict__ eps, const float* __restrict__ sigma)
{
    int bg = blockIdx.z;           // b*8+g
    int g = bg & 7;
    int m0 = blockIdx.x * 64;
    int n0 = blockIdx.y * 64;
    const float* Qp = g_Q + (size_t)bg * Nn * Dd;
    const float* Kp = g_K + (size_t)bg * Nn * Dd;

    __shared__ float Qs[32][65];
    __shared__ float Ks[32][65];

    int tid = threadIdx.x;
    int tx = tid & 15, ty = tid >> 4;

    float acc[4][4];
#pragma unroll
    for (int i = 0; i < 4; i++)
#pragma unroll
        for (int j = 0; j < 4; j++) acc[i][j] = 0.f;

    for (int k0 = 0; k0 < 96; k0 += 32) {
#pragma unroll
        for (int u = 0; u < 2; u++) {
            int f = tid + u * 256;      // 0..511
            int row = f >> 3;           // 0..63
            int c = (f & 7) * 4;        // 0..28
            float4 qv = *(const float4*)(Qp + (size_t)(n0 + row) * 96 + k0 + c);
            Qs[c + 0][row] = qv.x; Qs[c + 1][row] = qv.y;
            Qs[c + 2][row] = qv.z; Qs[c + 3][row] = qv.w;
            float4 kv = *(const float4*)(Kp + (size_t)(m0 + row) * 96 + k0 + c);
            Ks[c + 0][row] = kv.x; Ks[c + 1][row] = kv.y;
            Ks[c + 2][row] = kv.z; Ks[c + 3][row] = kv.w;
        }
        __syncthreads();
#pragma unroll
        for (int kk = 0; kk < 32; kk++) {
            float qr[4], kr[4];
#pragma unroll
            for (int i = 0; i < 4; i++) qr[i] = Qs[kk][ty + i * 16];
#pragma unroll
            for (int j = 0; j < 4; j++) kr[j] = Ks[kk][tx + j * 16];
#pragma unroll
            for (int i = 0; i < 4; i++)
#pragma unroll
                for (int j = 0; j < 4; j++)
                    acc[i][j] = fmaf(qr[i], kr[j], acc[i][j]);
        }
        __syncthreads();
    }

    float s2 = sigma[g];
    s2 = s2 * s2;
#pragma unroll
    for (int i = 0; i < 4; i++) {
        int n = n0 + ty + i * 16;
#pragma unroll
        for (int j = 0; j < 4; j++) {
            int m = m0 + tx + j * 16;
            size_t idx = ((size_t)bg * Nn + n) * Nn + m;
            g_S[idx] = acc[i][j] + s2 * eps[idx];
        }
    }
}

// ---------------------------------------------------------------------------
// K3: per (b,n): logits_l[m] = mish(sum_g S[b,g,n,m]*p[g,l])*scale + bias[b,n,m]
//     then softmax over m per l; write A[b,l,n,m].  512 threads = one m each.
// ---------------------------------------------------------------------------
__global__ void __launch_bounds__(512) mix_softmax_kernel(
    const float* __restrict__ encoding_bias, const float* __restrict__ p)
{
    int bn = blockIdx.x;
    int b = bn >> 9, n = bn & 511;
    int tid = threadIdx.x;          // m
    int lane = tid & 31, warp = tid >> 5;   // 16 warps

    __shared__ float ps[128];
    __shared__ float red[16][17];
    __shared__ float rmax[16];
    __shared__ float rsum[16];

    if (tid < 128) ps[tid] = p[tid];
    __syncthreads();

    float s[8];
#pragma unroll
    for (int g = 0; g < 8; g++)
        s[g] = g_S[(((size_t)(b * 8 + g)) * 512 + n) * 512 + tid];
    float bias = encoding_bias[((size_t)bn) * 512 + tid];
    const float scale = 0.03608439182435161f;   // 768^-0.5

    float vals[16];
#pragma unroll
    for (int l = 0; l < 16; l++) {
        float t = 0.f;
#pragma unroll
        for (int g = 0; g < 8; g++) t = fmaf(s[g], ps[g * 16 + l], t);
        // mish(t) = t * tanh(softplus(t)) = t*(e^2t + 2e^t)/(e^2t + 2e^t + 2)
        float e = __expf(fminf(t, 15.f));
        float num = e * (e + 2.f);
        float mish = t * (num / (num + 2.f));
        vals[l] = mish * scale + bias;
    }

    // --- block max per l ---
#pragma unroll
    for (int l = 0; l < 16; l++) {
        float v = vals[l];
#pragma unroll
        for (int o = 16; o > 0; o >>= 1)
            v = fmaxf(v, __shfl_xor_sync(0xffffffffu, v, o));
        if (lane == 0) red[l][warp] = v;
    }
    __syncthreads();
    {
        float v = (lane < 16) ? red[warp][lane] : -3.0e38f;
#pragma unroll
        for (int o = 8; o > 0; o >>= 1)
            v = fmaxf(v, __shfl_xor_sync(0xffffffffu, v, o));
        if (lane == 0) rmax[warp] = v;
    }
    __syncthreads();

    // --- exp + block sum per l ---
#pragma unroll
    for (int l = 0; l < 16; l++) {
        vals[l] = __expf(vals[l] - rmax[l]);
        float v = vals[l];
#pragma unroll
        for (int o = 16; o > 0; o >>= 1)
            v += __shfl_xor_sync(0xffffffffu, v, o);
        if (lane == 0) red[l][warp] = v;
    }
    __syncthreads();
    {
        float v = (lane < 16) ? red[warp][lane] : 0.f;
#pragma unroll
        for (int o = 8; o > 0; o >>= 1)
            v += __shfl_xor_sync(0xffffffffu, v, o);
        if (lane == 0) rsum[warp] = v;
    }
    __syncthreads();

#pragma unroll
    for (int l = 0; l < 16; l++) {
        float a = vals[l] / rsum[l];
        g_A[(((size_t)(b * 16 + l)) * 512 + n) * 512 + tid] = a;
    }
}

// ---------------------------------------------------------------------------
// K4: O[b,n,l*96+d] = sum_m A[b,l,n,m] * V[b,l,m,d]
// Per (b,l): 512x96 output, tiles 64(n) x 96(d), K(m)=512 in chunks of 32.
// 256 threads, 4x6 microtile.
// ---------------------------------------------------------------------------
__global__ void __launch_bounds__(256) outv_kernel()
{
    int bl = blockIdx.z;            // b*16+l
    int n0 = blockIdx.x * 64;
    const float* Ap = g_A + (size_t)bl * Nn * Nn;
    const float* Vp = g_V + (size_t)bl * Nn * Dd;

    __shared__ float As_[32][65];
    __shared__ float Vs[32][96];

    int tid = threadIdx.x;
    int tx = tid & 15, ty = tid >> 4;

    float acc[4][6];
#pragma unroll
    for (int i = 0; i < 4; i++)
#pragma unroll
        for (int j = 0; j < 6; j++) acc[i][j] = 0.f;

    for (int m0 = 0; m0 < 512; m0 += 32) {
#pragma unroll
        for (int u = 0; u < 2; u++) {
            int f = tid + u * 256;
            int row = f >> 3;          // 0..63 (n)
            int c = (f & 7) * 4;       // 0..28 (m)
            float4 av = *(const float4*)(Ap + (size_t)(n0 + row) * 512 + m0 + c);
            As_[c + 0][row] = av.x; As_[c + 1][row] = av.y;
            As_[c + 2][row] = av.z; As_[c + 3][row] = av.w;
        }
#pragma unroll
        for (int u = 0; u < 3; u++) {
            int f = tid + u * 256;     // 0..767
            int row = f / 24;          // 0..31 (m)
            int c = (f % 24) * 4;      // 0..92 (d)
            *(float4*)&Vs[row][c] = *(const float4*)(Vp + (size_t)(m0 + row) * 96 + c);
        }
        __syncthreads();
#pragma unroll
        for (int kk = 0; kk < 32; kk++) {
            float ar[4], vr[6];
#pragma unroll
            for (int i = 0; i < 4; i++) ar[i] = As_[kk][ty + i * 16];
#pragma unroll
            for (int j = 0; j < 6; j++) vr[j] = Vs[kk][tx + j * 16];
#pragma unroll
            for (int i = 0; i < 4; i++)
#pragma unroll
                for (int j = 0; j < 6; j++)
                    acc[i][j] = fmaf(ar[i], vr[j], acc[i][j]);
        }
        __syncthreads();
    }

    int b = bl >> 4, l = bl & 15;
#pragma unroll
    for (int i = 0; i < 4; i++) {
        int n = n0 + ty + i * 16;
#pragma unroll
        for (int j = 0; j < 6; j++) {
            int d = tx + j * 16;
            g_O[((size_t)(b * 512 + n)) * 1536 + l * 96 + d] = acc[i][j];
        }
    }
}

// ---------------------------------------------------------------------------
extern "C" void kernel_launch(void* const* d_in, const int* in_sizes, int n_in,
                              void* d_out, int out_size)
{
    const float* x     = (const float*)d_in[0];
    const float* ebias = (const float*)d_in[1];
    const float* eps   = (const float*)d_in[2];
    const float* Wq    = (const float*)d_in[3];
    const float* Wk    = (const float*)d_in[4];
    const float* Wv    = (const float*)d_in[5];
    const float* bv    = (const float*)d_in[6];
    const float* sigma = (const float*)d_in[7];
    const float* p     = (const float*)d_in[8];
    const float* Wout  = (const float*)d_in[9];
    float* out = (float*)d_out;

    float *Qd, *Kd, *Vd, *Od;
    cudaGetSymbolAddress((void**)&Qd, g_Q);
    cudaGetSymbolAddress((void**)&Kd, g_K);
    cudaGetSymbolAddress((void**)&Vd, g_V);
    cudaGetSymbolAddress((void**)&Od, g_O);

    // K1: projections (permuted stores)
    sgemm_kernel<<<dim3(6, 64), 256>>>(x, Wq, nullptr, Qd, 8192, 768, 768, 8);
    sgemm_kernel<<<dim3(6, 64), 256>>>(x, Wk, nullptr, Kd, 8192, 768, 768, 8);
    sgemm_kernel<<<dim3(12, 64), 256>>>(x, Wv, bv, Vd, 8192, 768, 1536, 16);

    // K2: attention scores + sigma^2*eps
    scores_kernel<<<dim3(8, 8, Bb * Gg), 256>>>(eps, sigma);

    // K3: group->L mix, mish, scale+bias, softmax
    mix_softmax_kernel<<<Bb * Nn, 512>>>(ebias, p);

    // K4: O = A @ V
    outv_kernel<<<dim3(8, 1, Bb * Ll), 256>>>();

    // K5: output projection (plain store into d_out)
    sgemm_kernel<<<dim3(6, 64), 256>>>(Od, Wout, nullptr, out, 8192, 1536, 768, 0);
}

// round 2
// speedup vs baseline: 1.3845x; 1.3845x over previous
#include <cuda_runtime.h>
#include <math.h>

// Problem constants
#define Bb 16
#define Nn 512
#define Hh 768
#define Gg 8
#define Dd 96
#define Ll 16
#define LDIM 1536

// Scratch (device globals -- allocation-free rule)
__device__ float g_Q[(size_t)Bb * Gg * Nn * Dd];          // [b][g][n][d]
__device__ float g_K[(size_t)Bb * Gg * Nn * Dd];          // [b][g][m][d]
__device__ float g_V[(size_t)Bb * Ll * Nn * Dd];          // [b][l][m][d]
__device__ float g_S[(size_t)Bb * Gg * Nn * Nn];          // [b][g][n][m]
__device__ float g_A[(size_t)Bb * Ll * Nn * Nn];          // [b][l][n][m]
__device__ float g_O[(size_t)Bb * Nn * LDIM];             // [b][n][l*d]

// ---------------------------------------------------------------------------
// tf32 helpers
// ---------------------------------------------------------------------------
__device__ __forceinline__ unsigned f2tf(float f) {
    unsigned u;
    asm("cvt.rna.tf32.f32 %0, %1;" : "=r"(u) : "f"(f));
    return u;
}

__device__ __forceinline__ void mma8(float c[4], const unsigned a[4], const unsigned b[2]) {
    asm volatile(
        "mma.sync.aligned.m16n8k8.row.col.f32.tf32.tf32.f32 "
        "{%0,%1,%2,%3}, {%4,%5,%6,%7}, {%8,%9}, {%0,%1,%2,%3};\n"
        : "+f"(c[0]), "+f"(c[1]), "+f"(c[2]), "+f"(c[3])
        : "r"(a[0]), "r"(a[1]), "r"(a[2]), "r"(a[3]), "r"(b[0]), "r"(b[1]));
}

// split a float into hi(tf32) and lo(tf32 of residual)
__device__ __forceinline__ void tfsplit(float f, unsigned& hi, unsigned& lo) {
    hi = f2tf(f);
    lo = f2tf(f - __uint_as_float(hi));
}

// ---------------------------------------------------------------------------
// Generic C = X(MxK) @ W(KxN) [+bias], tf32 mma, BM=64 BN=128, 256 threads.
// HEADS>0: permuted store into [b][head][n][96]; HEADS==0: plain row-major.
// SPLIT==3: 3xTF32 (fp32-accurate); SPLIT==1: plain tf32.
// Requires M%64==0, N%128==0, K%8==0.
// ---------------------------------------------------------------------------
template<int SPLIT, int HEADS, bool BIAS>
__global__ void __launch_bounds__(256) gemm_xw(
    const float* __restrict__ X, const float* __restrict__ W,
    const float* __restrict__ bias, float* __restrict__ out,
    int M, int K, int N)
{
    __shared__ __align__(16) float As[2][8][68];
    __shared__ __align__(16) float Bs[2][8][132];

    const int tid = threadIdx.x;
    const int warp = tid >> 5, lane = tid & 31;
    const int wm = warp >> 2, wn = warp & 3;      // 2 x 4 warp grid
    const int gid = lane >> 2, tig = lane & 3;

    const int m0 = blockIdx.y * 64;
    const int n0 = blockIdx.x * 128;

    const int aRow = tid >> 2;            // 0..63
    const int aK   = (tid & 3) << 1;      // 0,2,4,6
    const int bRow = tid >> 5;            // 0..7
    const int bCol = (tid & 31) << 2;     // 0..124

    float c[2][4][4];
#pragma unroll
    for (int mi = 0; mi < 2; mi++)
#pragma unroll
        for (int ni = 0; ni < 4; ni++)
#pragma unroll
            for (int q = 0; q < 4; q++) c[mi][ni][q] = 0.f;

    const int KT = K >> 3;

    float2 aReg = *(const float2*)(X + (size_t)(m0 + aRow) * K + aK);
    float4 bReg = *(const float4*)(W + (size_t)bRow * N + n0 + bCol);
    As[0][aK][aRow] = aReg.x;  As[0][aK + 1][aRow] = aReg.y;
    *(float4*)&Bs[0][bRow][bCol] = bReg;
    __syncthreads();

    for (int kt = 0; kt < KT; kt++) {
        const int cur = kt & 1;
        if (kt + 1 < KT) {
            const int k0 = (kt + 1) << 3;
            aReg = *(const float2*)(X + (size_t)(m0 + aRow) * K + k0 + aK);
            bReg = *(const float4*)(W + (size_t)(k0 + bRow) * N + n0 + bCol);
        }

        unsigned ah[2][4], al[2][4], bh[4][2], bl[4][2];
#pragma unroll
        for (int mi = 0; mi < 2; mi++) {
            const int rm = wm * 32 + mi * 16 + gid;
            float a0 = As[cur][tig][rm],     a1 = As[cur][tig][rm + 8];
            float a2 = As[cur][tig + 4][rm], a3 = As[cur][tig + 4][rm + 8];
            if (SPLIT == 3) {
                tfsplit(a0, ah[mi][0], al[mi][0]); tfsplit(a1, ah[mi][1], al[mi][1]);
                tfsplit(a2, ah[mi][2], al[mi][2]); tfsplit(a3, ah[mi][3], al[mi][3]);
            } else {
                ah[mi][0] = f2tf(a0); ah[mi][1] = f2tf(a1);
                ah[mi][2] = f2tf(a2); ah[mi][3] = f2tf(a3);
            }
        }
#pragma unroll
        for (int ni = 0; ni < 4; ni++) {
            const int cn = wn * 32 + ni * 8 + gid;
            float b0 = Bs[cur][tig][cn], b1 = Bs[cur][tig + 4][cn];
            if (SPLIT == 3) {
                tfsplit(b0, bh[ni][0], bl[ni][0]); tfsplit(b1, bh[ni][1], bl[ni][1]);
            } else {
                bh[ni][0] = f2tf(b0); bh[ni][1] = f2tf(b1);
            }
        }
#pragma unroll
        for (int mi = 0; mi < 2; mi++)
#pragma unroll
            for (int ni = 0; ni < 4; ni++) {
                mma8(c[mi][ni], ah[mi], bh[ni]);
                if (SPLIT == 3) {
                    mma8(c[mi][ni], ah[mi], bl[ni]);
                    mma8(c[mi][ni], al[mi], bh[ni]);
                }
            }

        if (kt + 1 < KT) {
            const int nxt = cur ^ 1;
            As[nxt][aK][aRow] = aReg.x;  As[nxt][aK + 1][aRow] = aReg.y;
            *(float4*)&Bs[nxt][bRow][bCol] = bReg;
            __syncthreads();
        }
    }

    // epilogue: float2 stores (cols tig*2, tig*2+1 are adjacent)
#pragma unroll
    for (int mi = 0; mi < 2; mi++) {
#pragma unroll
        for (int half = 0; half < 2; half++) {
            const int row = m0 + wm * 32 + mi * 16 + gid + half * 8;
            const int b = row >> 9, n = row & 511;
#pragma unroll
            for (int ni = 0; ni < 4; ni++) {
                const int col = n0 + wn * 32 + ni * 8 + tig * 2;
                float v0 = c[mi][ni][half * 2 + 0];
                float v1 = c[mi][ni][half * 2 + 1];
                if (BIAS) { v0 += bias[col]; v1 += bias[col + 1]; }
                if (HEADS > 0) {
                    const int h = col / 96;
                    const int d = col - h * 96;
                    float2* dst = (float2*)(out + (((size_t)(b * HEADS + h)) * 512 + n) * 96 + d);
                    *dst = make_float2(v0, v1);
                } else {
                    float2* dst = (float2*)(out + (size_t)row * N + col);
                    *dst = make_float2(v0, v1);
                }
            }
        }
    }
}

// ---------------------------------------------------------------------------
// Scores: S[bg,n,m] = sum_d Q[bg,n,d]*K[bg,m,d] + sigma[g]^2 * eps[bg,n,m]
// Batched tf32 mma (1x). BM=64 (n), BN=128 (m), K=96.
// ---------------------------------------------------------------------------
__global__ void __launch_bounds__(256) scores_mma(
    const float* __restrict__ eps, const float* __restrict__ sigma)
{
    __shared__ __align__(16) float As[2][8][68];
    __shared__ __align__(16) float Bs[2][8][132];

    const int tid = threadIdx.x;
    const int warp = tid >> 5, lane = tid & 31;
    const int wm = warp >> 2, wn = warp & 3;
    const int gid = lane >> 2, tig = lane & 3;

    const int bg = blockIdx.z;
    const int sn0 = blockIdx.y * 64;
    const int sm0 = blockIdx.x * 128;
    const float* Qp = g_Q + (size_t)bg * Nn * Dd;
    const float* Kp = g_K + (size_t)bg * Nn * Dd;

    const int aRow = tid >> 2;            // n: 0..63
    const int aK   = (tid & 3) << 1;      // d off
    const int bM   = tid >> 1;            // m: 0..127
    const int bD   = (tid & 1) << 2;      // d off 0/4

    float c[2][4][4];
#pragma unroll
    for (int mi = 0; mi < 2; mi++)
#pragma unroll
        for (int ni = 0; ni < 4; ni++)
#pragma unroll
            for (int q = 0; q < 4; q++) c[mi][ni][q] = 0.f;

    {
        float2 av = *(const float2*)(Qp + (size_t)(sn0 + aRow) * 96 + aK);
        float4 kv = *(const float4*)(Kp + (size_t)(sm0 + bM) * 96 + bD);
        As[0][aK][aRow] = av.x; As[0][aK + 1][aRow] = av.y;
        Bs[0][bD + 0][bM] = kv.x; Bs[0][bD + 1][bM] = kv.y;
        Bs[0][bD + 2][bM] = kv.z; Bs[0][bD + 3][bM] = kv.w;
    }
    __syncthreads();

    float2 aReg; float4 bReg;
    for (int kt = 0; kt < 12; kt++) {
        const int cur = kt & 1;
        if (kt + 1 < 12) {
            const int k0 = (kt + 1) << 3;
            aReg = *(const float2*)(Qp + (size_t)(sn0 + aRow) * 96 + k0 + aK);
            bReg = *(const float4*)(Kp + (size_t)(sm0 + bM) * 96 + k0 + bD);
        }

        unsigned ah[2][4], bh[4][2];
#pragma unroll
        for (int mi = 0; mi < 2; mi++) {
            const int rm = wm * 32 + mi * 16 + gid;
            ah[mi][0] = f2tf(As[cur][tig][rm]);
            ah[mi][1] = f2tf(As[cur][tig][rm + 8]);
            ah[mi][2] = f2tf(As[cur][tig + 4][rm]);
            ah[mi][3] = f2tf(As[cur][tig + 4][rm + 8]);
        }
#pragma unroll
        for (int ni = 0; ni < 4; ni++) {
            const int cn = wn * 32 + ni * 8 + gid;
            bh[ni][0] = f2tf(Bs[cur][tig][cn]);
            bh[ni][1] = f2tf(Bs[cur][tig + 4][cn]);
        }
#pragma unroll
        for (int mi = 0; mi < 2; mi++)
#pragma unroll
            for (int ni = 0; ni < 4; ni++)
                mma8(c[mi][ni], ah[mi], bh[ni]);

        if (kt + 1 < 12) {
            const int nxt = cur ^ 1;
            As[nxt][aK][aRow] = aReg.x; As[nxt][aK + 1][aRow] = aReg.y;
            Bs[nxt][bD + 0][bM] = bReg.x; Bs[nxt][bD + 1][bM] = bReg.y;
            Bs[nxt][bD + 2][bM] = bReg.z; Bs[nxt][bD + 3][bM] = bReg.w;
            __syncthreads();
        }
    }

    float s2 = sigma[bg & 7];
    s2 = s2 * s2;
#pragma unroll
    for (int mi = 0; mi < 2; mi++)
#pragma unroll
        for (int half = 0; half < 2; half++) {
            const int n = sn0 + wm * 32 + mi * 16 + gid + half * 8;
#pragma unroll
            for (int ni = 0; ni < 4; ni++) {
                const int m = sm0 + wn * 32 + ni * 8 + tig * 2;
                const size_t idx = ((size_t)bg * Nn + n) * Nn + m;
                float2 ev = *(const float2*)(eps + idx);
                float2 r;
                r.x = c[mi][ni][half * 2 + 0] + s2 * ev.x;
                r.y = c[mi][ni][half * 2 + 1] + s2 * ev.y;
                *(float2*)(g_S + idx) = r;
            }
        }
}

// ---------------------------------------------------------------------------
// O = A @ V per (b,l): (512n x 512m) @ (512m x 96d). 3xTF32.
// BM=64 (n), BN=96 (d), warp tile 32x24.
// ---------------------------------------------------------------------------
__global__ void __launch_bounds__(256) outv_mma()
{
    __shared__ __align__(16) float As[2][8][68];
    __shared__ __align__(16) float Bs[2][8][100];

    const int tid = threadIdx.x;
    const int warp = tid >> 5, lane = tid & 31;
    const int wm = warp >> 2, wn = warp & 3;
    const int gid = lane >> 2, tig = lane & 3;

    const int bl = blockIdx.z;
    const int n0 = blockIdx.y * 64;
    const float* Ap = g_A + (size_t)bl * Nn * Nn;
    const float* Vp = g_V + (size_t)bl * Nn * Dd;

    const int aRow = tid >> 2;            // n 0..63
    const int aK   = (tid & 3) << 1;      // m off
    const int vRow = tid / 24;            // k(m) 0..7  (threads <192)
    const int vCol = (tid % 24) << 2;     // d 0..92
    const bool vAct = tid < 192;

    float c[2][3][4];
#pragma unroll
    for (int mi = 0; mi < 2; mi++)
#pragma unroll
        for (int ni = 0; ni < 3; ni++)
#pragma unroll
            for (int q = 0; q < 4; q++) c[mi][ni][q] = 0.f;

    {
        float2 av = *(const float2*)(Ap + (size_t)(n0 + aRow) * 512 + aK);
        As[0][aK][aRow] = av.x; As[0][aK + 1][aRow] = av.y;
        if (vAct) {
            float4 vv = *(const float4*)(Vp + (size_t)vRow * 96 + vCol);
            *(float4*)&Bs[0][vRow][vCol] = vv;
        }
    }
    __syncthreads();

    float2 aReg; float4 bReg;
    for (int kt = 0; kt < 64; kt++) {
        const int cur = kt & 1;
        if (kt + 1 < 64) {
            const int k0 = (kt + 1) << 3;
            aReg = *(const float2*)(Ap + (size_t)(n0 + aRow) * 512 + k0 + aK);
            if (vAct) bReg = *(const float4*)(Vp + (size_t)(k0 + vRow) * 96 + vCol);
        }

        unsigned ah[2][4], al[2][4], bh[3][2], bl_[3][2];
#pragma unroll
        for (int mi = 0; mi < 2; mi++) {
            const int rm = wm * 32 + mi * 16 + gid;
            tfsplit(As[cur][tig][rm],         ah[mi][0], al[mi][0]);
            tfsplit(As[cur][tig][rm + 8],     ah[mi][1], al[mi][1]);
            tfsplit(As[cur][tig + 4][rm],     ah[mi][2], al[mi][2]);
            tfsplit(As[cur][tig + 4][rm + 8], ah[mi][3], al[mi][3]);
        }
#pragma unroll
        for (int ni = 0; ni < 3; ni++) {
            const int cn = wn * 24 + ni * 8 + gid;
            tfsplit(Bs[cur][tig][cn],     bh[ni][0], bl_[ni][0]);
            tfsplit(Bs[cur][tig + 4][cn], bh[ni][1], bl_[ni][1]);
        }
#pragma unroll
        for (int mi = 0; mi < 2; mi++)
#pragma unroll
            for (int ni = 0; ni < 3; ni++) {
                mma8(c[mi][ni], ah[mi], bh[ni]);
                mma8(c[mi][ni], ah[mi], bl_[ni]);
                mma8(c[mi][ni], al[mi], bh[ni]);
            }

        if (kt + 1 < 64) {
            const int nxt = cur ^ 1;
            As[nxt][aK][aRow] = aReg.x; As[nxt][aK + 1][aRow] = aReg.y;
            if (vAct) *(float4*)&Bs[nxt][vRow][vCol] = bReg;
            __syncthreads();
        }
    }

    const int b = bl >> 4, l = bl & 15;
#pragma unroll
    for (int mi = 0; mi < 2; mi++)
#pragma unroll
        for (int half = 0; half < 2; half++) {
            const int n = n0 + wm * 32 + mi * 16 + gid + half * 8;
#pragma unroll
            for (int ni = 0; ni < 3; ni++) {
                const int d = wn * 24 + ni * 8 + tig * 2;
                float2* dst = (float2*)(g_O + ((size_t)(b * 512 + n)) * 1536 + l * 96 + d);
                *dst = make_float2(c[mi][ni][half * 2 + 0], c[mi][ni][half * 2 + 1]);
            }
        }
}

// ---------------------------------------------------------------------------
// K3: per (b,n): logits_l[m] = mish(sum_g S[b,g,n,m]*p[g,l])*scale + bias[b,n,m]
//     then softmax over m per l; write A[b,l,n,m].  512 threads = one m each.
// ---------------------------------------------------------------------------
__global__ void __launch_bounds__(512) mix_softmax_kernel(
    const float* __restrict__ encoding_bias, const float* __restrict__ p)
{
    int bn = blockIdx.x;
    int b = bn >> 9, n = bn & 511;
    int tid = threadIdx.x;          // m
    int lane = tid & 31, warp = tid >> 5;   // 16 warps

    __shared__ float ps[128];
    __shared__ float red[16][17];
    __shared__ float rmax[16];
    __shared__ float rsum[16];

    if (tid < 128) ps[tid] = p[tid];
    __syncthreads();

    float s[8];
#pragma unroll
    for (int g = 0; g < 8; g++)
        s[g] = g_S[(((size_t)(b * 8 + g)) * 512 + n) * 512 + tid];
    float bias = encoding_bias[((size_t)bn) * 512 + tid];
    const float scale = 0.03608439182435161f;   // 768^-0.5

    float vals[16];
#pragma unroll
    for (int l = 0; l < 16; l++) {
        float t = 0.f;
#pragma unroll
        for (int g = 0; g < 8; g++) t = fmaf(s[g], ps[g * 16 + l], t);
        float e = __expf(fminf(t, 15.f));
        float num = e * (e + 2.f);
        float mish = t * (num / (num + 2.f));
        vals[l] = mish * scale + bias;
    }

#pragma unroll
    for (int l = 0; l < 16; l++) {
        float v = vals[l];
#pragma unroll
        for (int o = 16; o > 0; o >>= 1)
            v = fmaxf(v, __shfl_xor_sync(0xffffffffu, v, o));
        if (lane == 0) red[l][warp] = v;
    }
    __syncthreads();
    {
        float v = (lane < 16) ? red[warp][lane] : -3.0e38f;
#pragma unroll
        for (int o = 8; o > 0; o >>= 1)
            v = fmaxf(v, __shfl_xor_sync(0xffffffffu, v, o));
        if (lane == 0) rmax[warp] = v;
    }
    __syncthreads();

#pragma unroll
    for (int l = 0; l < 16; l++) {
        vals[l] = __expf(vals[l] - rmax[l]);
        float v = vals[l];
#pragma unroll
        for (int o = 16; o > 0; o >>= 1)
            v += __shfl_xor_sync(0xffffffffu, v, o);
        if (lane == 0) red[l][warp] = v;
    }
    __syncthreads();
    {
        float v = (lane < 16) ? red[warp][lane] : 0.f;
#pragma unroll
        for (int o = 8; o > 0; o >>= 1)
            v += __shfl_xor_sync(0xffffffffu, v, o);
        if (lane == 0) rsum[warp] = v;
    }
    __syncthreads();

#pragma unroll
    for (int l = 0; l < 16; l++) {
        float a = vals[l] / rsum[l];
        g_A[(((size_t)(b * 16 + l)) * 512 + n) * 512 + tid] = a;
    }
}

// ---------------------------------------------------------------------------
extern "C" void kernel_launch(void* const* d_in, const int* in_sizes, int n_in,
                              void* d_out, int out_size)
{
    const float* x     = (const float*)d_in[0];
    const float* ebias = (const float*)d_in[1];
    const float* eps   = (const float*)d_in[2];
    const float* Wq    = (const float*)d_in[3];
    const float* Wk    = (const float*)d_in[4];
    const float* Wv    = (const float*)d_in[5];
    const float* bv    = (const float*)d_in[6];
    const float* sigma = (const float*)d_in[7];
    const float* p     = (const float*)d_in[8];
    const float* Wout  = (const float*)d_in[9];
    float* out = (float*)d_out;

    float *Qd, *Kd, *Vd, *Od;
    cudaGetSymbolAddress((void**)&Qd, g_Q);
    cudaGetSymbolAddress((void**)&Kd, g_K);
    cudaGetSymbolAddress((void**)&Vd, g_V);
    cudaGetSymbolAddress((void**)&Od, g_O);

    // Projections: Q,K (1x tf32, pre-softmax); V (3xTF32, post-softmax path)
    gemm_xw<1, 8,  false><<<dim3(6, 128), 256>>>(x, Wq, nullptr, Qd, 8192, 768, 768);
    gemm_xw<1, 8,  false><<<dim3(6, 128), 256>>>(x, Wk, nullptr, Kd, 8192, 768, 768);
    gemm_xw<3, 16, true ><<<dim3(12, 128), 256>>>(x, Wv, bv, Vd, 8192, 768, 1536);

    // Scores (1x tf32) + sigma^2*eps
    scores_mma<<<dim3(4, 8, Bb * Gg), 256>>>(eps, sigma);

    // Mix + mish + softmax (fp32)
    mix_softmax_kernel<<<Bb * Nn, 512>>>(ebias, p);

    // O = A @ V (3xTF32)
    outv_mma<<<dim3(1, 8, Bb * Ll), 256>>>();

    // Output projection (3xTF32)
    gemm_xw<3, 0, false><<<dim3(6, 128), 256>>>(Od, Wout, nullptr, out, 8192, 1536, 768);
}

// round 3
// speedup vs baseline: 1.9555x; 1.4124x over previous
#include <cuda_runtime.h>
#include <cuda_bf16.h>
#include <math.h>

#define Bb 16
#define Nn 512
#define Hh 768
#define Gg 8
#define Dd 96
#define Ll 16
#define LDIM 1536

// ---------------- scratch (device globals; u32 = lo<<16 | hi, both bf16) ---
__device__ unsigned g_x2[(size_t)8192 * 768];
__device__ unsigned g_Wq2[768 * 768];
__device__ unsigned g_Wk2[768 * 768];
__device__ unsigned g_Wv2[768 * 1536];
__device__ unsigned g_Wo2[1536 * 768];
__device__ unsigned g_Q2[(size_t)Bb * Gg * Nn * Dd];   // [bg][n][d]
__device__ unsigned g_K2[(size_t)Bb * Gg * Nn * Dd];   // [bg][m][d]
__device__ unsigned g_V2[(size_t)Bb * Ll * Nn * Dd];   // [bl][m][d]
__device__ float    g_S [(size_t)Bb * Gg * Nn * Nn];   // [bg][n][m]
__device__ unsigned g_A2[(size_t)Bb * Ll * Nn * Nn];   // [bl][n][m]
__device__ unsigned g_O2[(size_t)8192 * 1536];         // [b*512+n][l*96+d]

// ---------------- helpers --------------------------------------------------
__device__ __forceinline__ unsigned psplit(float v) {
    unsigned short h = __bfloat16_as_ushort(__float2bfloat16(v));
    float hv = __bfloat162float(__ushort_as_bfloat16(h));
    unsigned short l = __bfloat16_as_ushort(__float2bfloat16(v - hv));
    return ((unsigned)l << 16) | (unsigned)h;
}

__device__ __forceinline__ void ldsm4(unsigned f[4], unsigned addr) {
    asm volatile("ldmatrix.sync.aligned.m8n8.x4.shared.b16 {%0,%1,%2,%3}, [%4];"
                 : "=r"(f[0]), "=r"(f[1]), "=r"(f[2]), "=r"(f[3]) : "r"(addr));
}
__device__ __forceinline__ void ldsm4t(unsigned& r0, unsigned& r1, unsigned& r2,
                                       unsigned& r3, unsigned addr) {
    asm volatile("ldmatrix.sync.aligned.m8n8.x4.trans.shared.b16 {%0,%1,%2,%3}, [%4];"
                 : "=r"(r0), "=r"(r1), "=r"(r2), "=r"(r3) : "r"(addr));
}
__device__ __forceinline__ void ldsm2t(unsigned& r0, unsigned& r1, unsigned addr) {
    asm volatile("ldmatrix.sync.aligned.m8n8.x2.trans.shared.b16 {%0,%1}, [%2];"
                 : "=r"(r0), "=r"(r1) : "r"(addr));
}
__device__ __forceinline__ void mma16(float c[4], const unsigned a[4],
                                      unsigned b0, unsigned b1) {
    asm volatile(
        "mma.sync.aligned.m16n8k16.row.col.f32.bf16.bf16.f32 "
        "{%0,%1,%2,%3}, {%4,%5,%6,%7}, {%8,%9}, {%0,%1,%2,%3};"
        : "+f"(c[0]), "+f"(c[1]), "+f"(c[2]), "+f"(c[3])
        : "r"(a[0]), "r"(a[1]), "r"(a[2]), "r"(a[3]), "r"(b0), "r"(b1));
}
__device__ __forceinline__ unsigned sptr(const void* p) {
    return (unsigned)__cvta_generic_to_shared(p);
}

// ---------------- split inputs once ----------------------------------------
__global__ void __launch_bounds__(256) split4(const float4* __restrict__ in,
                                              uint4* __restrict__ out, int n4) {
    int i = blockIdx.x * 256 + threadIdx.x;
    if (i < n4) {
        float4 v = in[i];
        uint4 r;
        r.x = psplit(v.x); r.y = psplit(v.y); r.z = psplit(v.z); r.w = psplit(v.w);
        out[i] = r;
    }
}

// ---------------------------------------------------------------------------
// Core GEMM: C[MxN] = A2[MxK] @ B2[KxN], bf16-split pairs, BM=128 BN=64 BK=16.
// 8 warps (4m x 2n), warp tile 32x32.  HEADS>0: split-pair permuted store
// into [b][head][n][96]; HEADS==0: plain fp32 store.
// ---------------------------------------------------------------------------
template<int HEADS, bool BIAS>
__global__ void __launch_bounds__(256) gemm_bf(
    const unsigned* __restrict__ A2, const unsigned* __restrict__ B2,
    const float* __restrict__ bias, void* __restrict__ outp, int K, int N)
{
    __shared__ __align__(16) __nv_bfloat16 Ah[128][24], Al[128][24];
    __shared__ __align__(16) __nv_bfloat16 Bh[16][72],  Bl[16][72];

    const int tid = threadIdx.x;
    const int lane = tid & 31, warp = tid >> 5;
    const int wm = warp >> 1, wn = warp & 1;
    const int gid = lane >> 2, tig = lane & 3;
    const int m0 = blockIdx.y * 128, n0 = blockIdx.x * 64;

    const int aR = tid >> 1, aC = (tid & 1) * 8;
    const int bK = tid >> 4, bN = (tid & 15) * 4;

    float c[2][4][4];
#pragma unroll
    for (int i = 0; i < 2; i++)
#pragma unroll
        for (int j = 0; j < 4; j++)
#pragma unroll
            for (int q = 0; q < 4; q++) c[i][j][q] = 0.f;

    const unsigned adAh = sptr(&Ah[wm * 32 + (lane & 15)][(lane >> 4) * 8]);
    const unsigned adAl = sptr(&Al[wm * 32 + (lane & 15)][(lane >> 4) * 8]);
    const unsigned adBh = sptr(&Bh[lane & 15][wn * 32 + (lane >> 4) * 8]);
    const unsigned adBl = sptr(&Bl[lane & 15][wn * 32 + (lane >> 4) * 8]);

    uint4 av0, av1, bv;
    const int KT = K >> 4;

    auto loadg = [&](int k0) {
        av0 = *(const uint4*)(A2 + (size_t)(m0 + aR) * K + k0 + aC);
        av1 = *(const uint4*)(A2 + (size_t)(m0 + aR) * K + k0 + aC + 4);
        bv  = *(const uint4*)(B2 + (size_t)(k0 + bK) * N + n0 + bN);
    };
    auto stores = [&]() {
        *(unsigned*)&Ah[aR][aC]     = ((av0.y & 0xffffu) << 16) | (av0.x & 0xffffu);
        *(unsigned*)&Ah[aR][aC + 2] = ((av0.w & 0xffffu) << 16) | (av0.z & 0xffffu);
        *(unsigned*)&Ah[aR][aC + 4] = ((av1.y & 0xffffu) << 16) | (av1.x & 0xffffu);
        *(unsigned*)&Ah[aR][aC + 6] = ((av1.w & 0xffffu) << 16) | (av1.z & 0xffffu);
        *(unsigned*)&Al[aR][aC]     = (av0.y & 0xffff0000u) | (av0.x >> 16);
        *(unsigned*)&Al[aR][aC + 2] = (av0.w & 0xffff0000u) | (av0.z >> 16);
        *(unsigned*)&Al[aR][aC + 4] = (av1.y & 0xffff0000u) | (av1.x >> 16);
        *(unsigned*)&Al[aR][aC + 6] = (av1.w & 0xffff0000u) | (av1.z >> 16);
        *(unsigned*)&Bh[bK][bN]     = ((bv.y & 0xffffu) << 16) | (bv.x & 0xffffu);
        *(unsigned*)&Bh[bK][bN + 2] = ((bv.w & 0xffffu) << 16) | (bv.z & 0xffffu);
        *(unsigned*)&Bl[bK][bN]     = (bv.y & 0xffff0000u) | (bv.x >> 16);
        *(unsigned*)&Bl[bK][bN + 2] = (bv.w & 0xffff0000u) | (bv.z >> 16);
    };

    loadg(0); stores(); __syncthreads();

    for (int kt = 0; kt < KT; kt++) {
        if (kt + 1 < KT) loadg((kt + 1) << 4);

        unsigned ah[2][4], al[2][4], bh[4][2], bl[4][2], t0, t1, t2, t3;
        ldsm4(ah[0], adAh);        ldsm4(ah[1], adAh + 768);
        ldsm4(al[0], adAl);        ldsm4(al[1], adAl + 768);
        ldsm4t(t0, t1, t2, t3, adBh);
        bh[0][0] = t0; bh[0][1] = t1; bh[1][0] = t2; bh[1][1] = t3;
        ldsm4t(t0, t1, t2, t3, adBh + 32);
        bh[2][0] = t0; bh[2][1] = t1; bh[3][0] = t2; bh[3][1] = t3;
        ldsm4t(t0, t1, t2, t3, adBl);
        bl[0][0] = t0; bl[0][1] = t1; bl[1][0] = t2; bl[1][1] = t3;
        ldsm4t(t0, t1, t2, t3, adBl + 32);
        bl[2][0] = t0; bl[2][1] = t1; bl[3][0] = t2; bl[3][1] = t3;

#pragma unroll
        for (int mf = 0; mf < 2; mf++)
#pragma unroll
            for (int nf = 0; nf < 4; nf++) {
                mma16(c[mf][nf], ah[mf], bh[nf][0], bh[nf][1]);
                mma16(c[mf][nf], ah[mf], bl[nf][0], bl[nf][1]);
                mma16(c[mf][nf], al[mf], bh[nf][0], bh[nf][1]);
            }

        __syncthreads();
        if (kt + 1 < KT) { stores(); __syncthreads(); }
    }

#pragma unroll
    for (int mf = 0; mf < 2; mf++)
#pragma unroll
        for (int q2 = 0; q2 < 2; q2++) {
            const int row = m0 + wm * 32 + mf * 16 + gid + q2 * 8;
            const int b = row >> 9, n = row & 511;
#pragma unroll
            for (int nf = 0; nf < 4; nf++) {
                const int col = n0 + wn * 32 + nf * 8 + tig * 2;
                float v0 = c[mf][nf][q2 * 2 + 0];
                float v1 = c[mf][nf][q2 * 2 + 1];
                if (BIAS) { v0 += bias[col]; v1 += bias[col + 1]; }
                if (HEADS > 0) {
                    const int h = col / 96, d = col - h * 96;
                    unsigned* dst = (unsigned*)outp +
                        (((size_t)(b * HEADS + h)) * 512 + n) * 96 + d;
                    *(uint2*)dst = make_uint2(psplit(v0), psplit(v1));
                } else {
                    *(float2*)((float*)outp + (size_t)row * N + col) =
                        make_float2(v0, v1);
                }
            }
        }
}

// ---------------------------------------------------------------------------
// Scores: S[bg,n,m] = Q.K^T + sigma^2*eps. BM=BN=64, 128 thr (2x2 warps),
// both operands row-major over d -> non-trans ldmatrix both sides.
// ---------------------------------------------------------------------------
__global__ void __launch_bounds__(128) scores_bf(
    const float* __restrict__ eps, const float* __restrict__ sigma)
{
    __shared__ __align__(16) __nv_bfloat16 Qh[64][24], Ql[64][24];
    __shared__ __align__(16) __nv_bfloat16 Kh[64][24], Kl[64][24];

    const int tid = threadIdx.x;
    const int lane = tid & 31, warp = tid >> 5;
    const int wm = warp >> 1, wn = warp & 1;
    const int gid = lane >> 2, tig = lane & 3;
    const int bg = blockIdx.z;
    const int sn0 = blockIdx.y * 64, sm0 = blockIdx.x * 64;

    const unsigned* Qp = g_Q2 + (size_t)bg * Nn * Dd;
    const unsigned* Kp = g_K2 + (size_t)bg * Nn * Dd;

    const int aR = tid >> 1, aC = (tid & 1) * 8;

    float c[2][4][4];
#pragma unroll
    for (int i = 0; i < 2; i++)
#pragma unroll
        for (int j = 0; j < 4; j++)
#pragma unroll
            for (int q = 0; q < 4; q++) c[i][j][q] = 0.f;

    const unsigned adQh = sptr(&Qh[wm * 32 + (lane & 15)][(lane >> 4) * 8]);
    const unsigned adQl = sptr(&Ql[wm * 32 + (lane & 15)][(lane >> 4) * 8]);
    const unsigned adKh = sptr(&Kh[wn * 32 + (lane & 15)][(lane >> 4) * 8]);
    const unsigned adKl = sptr(&Kl[wn * 32 + (lane & 15)][(lane >> 4) * 8]);

    uint4 q0, q1, k0v, k1v;
    auto loadg = [&](int k0) {
        q0  = *(const uint4*)(Qp + (size_t)(sn0 + aR) * 96 + k0 + aC);
        q1  = *(const uint4*)(Qp + (size_t)(sn0 + aR) * 96 + k0 + aC + 4);
        k0v = *(const uint4*)(Kp + (size_t)(sm0 + aR) * 96 + k0 + aC);
        k1v = *(const uint4*)(Kp + (size_t)(sm0 + aR) * 96 + k0 + aC + 4);
    };
    auto stores = [&]() {
        *(unsigned*)&Qh[aR][aC]     = ((q0.y & 0xffffu) << 16) | (q0.x & 0xffffu);
        *(unsigned*)&Qh[aR][aC + 2] = ((q0.w & 0xffffu) << 16) | (q0.z & 0xffffu);
        *(unsigned*)&Qh[aR][aC + 4] = ((q1.y & 0xffffu) << 16) | (q1.x & 0xffffu);
        *(unsigned*)&Qh[aR][aC + 6] = ((q1.w & 0xffffu) << 16) | (q1.z & 0xffffu);
        *(unsigned*)&Ql[aR][aC]     = (q0.y & 0xffff0000u) | (q0.x >> 16);
        *(unsigned*)&Ql[aR][aC + 2] = (q0.w & 0xffff0000u) | (q0.z >> 16);
        *(unsigned*)&Ql[aR][aC + 4] = (q1.y & 0xffff0000u) | (q1.x >> 16);
        *(unsigned*)&Ql[aR][aC + 6] = (q1.w & 0xffff0000u) | (q1.z >> 16);
        *(unsigned*)&Kh[aR][aC]     = ((k0v.y & 0xffffu) << 16) | (k0v.x & 0xffffu);
        *(unsigned*)&Kh[aR][aC + 2] = ((k0v.w & 0xffffu) << 16) | (k0v.z & 0xffffu);
        *(unsigned*)&Kh[aR][aC + 4] = ((k1v.y & 0xffffu) << 16) | (k1v.x & 0xffffu);
        *(unsigned*)&Kh[aR][aC + 6] = ((k1v.w & 0xffffu) << 16) | (k1v.z & 0xffffu);
        *(unsigned*)&Kl[aR][aC]     = (k0v.y & 0xffff0000u) | (k0v.x >> 16);
        *(unsigned*)&Kl[aR][aC + 2] = (k0v.w & 0xffff0000u) | (k0v.z >> 16);
        *(unsigned*)&Kl[aR][aC + 4] = (k1v.y & 0xffff0000u) | (k1v.x >> 16);
        *(unsigned*)&Kl[aR][aC + 6] = (k1v.w & 0xffff0000u) | (k1v.z >> 16);
    };

    loadg(0); stores(); __syncthreads();

    for (int kt = 0; kt < 6; kt++) {
        if (kt + 1 < 6) loadg((kt + 1) << 4);

        unsigned ah[2][4], al[2][4], f0[4], f1[4], bh[4][2], bl[4][2];
        ldsm4(ah[0], adQh);  ldsm4(ah[1], adQh + 768);
        ldsm4(al[0], adQl);  ldsm4(al[1], adQl + 768);
        // non-trans B: x4 over rows n..n+15 -> frag(n)=(r0,r2), frag(n+8)=(r1,r3)
        ldsm4(f0, adKh);     ldsm4(f1, adKh + 768);
        bh[0][0] = f0[0]; bh[0][1] = f0[2]; bh[1][0] = f0[1]; bh[1][1] = f0[3];
        bh[2][0] = f1[0]; bh[2][1] = f1[2]; bh[3][0] = f1[1]; bh[3][1] = f1[3];
        ldsm4(f0, adKl);     ldsm4(f1, adKl + 768);
        bl[0][0] = f0[0]; bl[0][1] = f0[2]; bl[1][0] = f0[1]; bl[1][1] = f0[3];
        bl[2][0] = f1[0]; bl[2][1] = f1[2]; bl[3][0] = f1[1]; bl[3][1] = f1[3];

#pragma unroll
        for (int mf = 0; mf < 2; mf++)
#pragma unroll
            for (int nf = 0; nf < 4; nf++) {
                mma16(c[mf][nf], ah[mf], bh[nf][0], bh[nf][1]);
                mma16(c[mf][nf], ah[mf], bl[nf][0], bl[nf][1]);
                mma16(c[mf][nf], al[mf], bh[nf][0], bh[nf][1]);
            }

        __syncthreads();
        if (kt + 1 < 6) { stores(); __syncthreads(); }
    }

    float s2 = sigma[bg & 7];
    s2 = s2 * s2;
#pragma unroll
    for (int mf = 0; mf < 2; mf++)
#pragma unroll
        for (int q2 = 0; q2 < 2; q2++) {
            const int n = sn0 + wm * 32 + mf * 16 + gid + q2 * 8;
#pragma unroll
            for (int nf = 0; nf < 4; nf++) {
                const int m = sm0 + wn * 32 + nf * 8 + tig * 2;
                const size_t idx = ((size_t)bg * Nn + n) * Nn + m;
                float2 ev = *(const float2*)(eps + idx);
                *(float2*)(g_S + idx) = make_float2(
                    c[mf][nf][q2 * 2 + 0] + s2 * ev.x,
                    c[mf][nf][q2 * 2 + 1] + s2 * ev.y);
            }
        }
}

// ---------------------------------------------------------------------------
// Mix + mish + softmax (fp32), writes A as split pairs.
// ---------------------------------------------------------------------------
__global__ void __launch_bounds__(512) mix_softmax_kernel(
    const float* __restrict__ encoding_bias, const float* __restrict__ p)
{
    int bn = blockIdx.x;
    int b = bn >> 9, n = bn & 511;
    int tid = threadIdx.x;
    int lane = tid & 31, warp = tid >> 5;

    __shared__ float ps[128];
    __shared__ float red[16][17];
    __shared__ float rmax[16];
    __shared__ float rsum[16];

    if (tid < 128) ps[tid] = p[tid];
    __syncthreads();

    float s[8];
#pragma unroll
    for (int g = 0; g < 8; g++)
        s[g] = g_S[(((size_t)(b * 8 + g)) * 512 + n) * 512 + tid];
    float bias = encoding_bias[((size_t)bn) * 512 + tid];
    const float scale = 0.03608439182435161f;

    float vals[16];
#pragma unroll
    for (int l = 0; l < 16; l++) {
        float t = 0.f;
#pragma unroll
        for (int g = 0; g < 8; g++) t = fmaf(s[g], ps[g * 16 + l], t);
        float e = __expf(fminf(t, 15.f));
        float num = e * (e + 2.f);
        float mish = t * (num / (num + 2.f));
        vals[l] = mish * scale + bias;
    }

#pragma unroll
    for (int l = 0; l < 16; l++) {
        float v = vals[l];
#pragma unroll
        for (int o = 16; o > 0; o >>= 1)
            v = fmaxf(v, __shfl_xor_sync(0xffffffffu, v, o));
        if (lane == 0) red[l][warp] = v;
    }
    __syncthreads();
    {
        float v = (lane < 16) ? red[warp][lane] : -3.0e38f;
#pragma unroll
        for (int o = 8; o > 0; o >>= 1)
            v = fmaxf(v, __shfl_xor_sync(0xffffffffu, v, o));
        if (lane == 0) rmax[warp] = v;
    }
    __syncthreads();

#pragma unroll
    for (int l = 0; l < 16; l++) {
        vals[l] = __expf(vals[l] - rmax[l]);
        float v = vals[l];
#pragma unroll
        for (int o = 16; o > 0; o >>= 1)
            v += __shfl_xor_sync(0xffffffffu, v, o);
        if (lane == 0) red[l][warp] = v;
    }
    __syncthreads();
    {
        float v = (lane < 16) ? red[warp][lane] : 0.f;
#pragma unroll
        for (int o = 8; o > 0; o >>= 1)
            v += __shfl_xor_sync(0xffffffffu, v, o);
        if (lane == 0) rsum[warp] = v;
    }
    __syncthreads();

#pragma unroll
    for (int l = 0; l < 16; l++) {
        g_A2[(((size_t)(b * 16 + l)) * 512 + n) * 512 + tid] =
            psplit(vals[l] / rsum[l]);
    }
}

// ---------------------------------------------------------------------------
// O = A @ V per (b,l): 512n x 96d, K(m)=512.  BM=64 BN=96, 256 thr (2x4),
// warp tile 32x24.  A row-major over m; V row-major [m][d] -> trans B.
// ---------------------------------------------------------------------------
__global__ void __launch_bounds__(256) outv_bf()
{
    __shared__ __align__(16) __nv_bfloat16 Aph[64][24], Apl[64][24];
    __shared__ __align__(16) __nv_bfloat16 Vh[16][104], Vl[16][104];

    const int tid = threadIdx.x;
    const int lane = tid & 31, warp = tid >> 5;
    const int wm = warp >> 2, wn = warp & 3;
    const int gid = lane >> 2, tig = lane & 3;
    const int bl = blockIdx.y;
    const int n0 = blockIdx.x * 64;

    const unsigned* Ap = g_A2 + (size_t)bl * Nn * Nn;
    const unsigned* Vp = g_V2 + (size_t)bl * Nn * Dd;

    const int aR = tid >> 2, aC = (tid & 3) * 4;
    const int vK = tid >> 4, vN = (tid & 15) * 6;

    float c[2][3][4];
#pragma unroll
    for (int i = 0; i < 2; i++)
#pragma unroll
        for (int j = 0; j < 3; j++)
#pragma unroll
            for (int q = 0; q < 4; q++) c[i][j][q] = 0.f;

    const unsigned adAh = sptr(&Aph[wm * 32 + (lane & 15)][(lane >> 4) * 8]);
    const unsigned adAl = sptr(&Apl[wm * 32 + (lane & 15)][(lane >> 4) * 8]);
    const unsigned adVh = sptr(&Vh[lane & 15][wn * 24 + (lane >> 4) * 8]);
    const unsigned adVl = sptr(&Vl[lane & 15][wn * 24 + (lane >> 4) * 8]);
    const unsigned adVh2 = sptr(&Vh[lane & 15][wn * 24 + 16]);
    const unsigned adVl2 = sptr(&Vl[lane & 15][wn * 24 + 16]);

    uint4 av;
    uint2 vv0, vv1, vv2;
    auto loadg = [&](int k0) {
        av  = *(const uint4*)(Ap + (size_t)(n0 + aR) * 512 + k0 + aC);
        vv0 = *(const uint2*)(Vp + (size_t)(k0 + vK) * 96 + vN);
        vv1 = *(const uint2*)(Vp + (size_t)(k0 + vK) * 96 + vN + 2);
        vv2 = *(const uint2*)(Vp + (size_t)(k0 + vK) * 96 + vN + 4);
    };
    auto stores = [&]() {
        *(unsigned*)&Aph[aR][aC]     = ((av.y & 0xffffu) << 16) | (av.x & 0xffffu);
        *(unsigned*)&Aph[aR][aC + 2] = ((av.w & 0xffffu) << 16) | (av.z & 0xffffu);
        *(unsigned*)&Apl[aR][aC]     = (av.y & 0xffff0000u) | (av.x >> 16);
        *(unsigned*)&Apl[aR][aC + 2] = (av.w & 0xffff0000u) | (av.z >> 16);
        *(unsigned*)&Vh[vK][vN]      = ((vv0.y & 0xffffu) << 16) | (vv0.x & 0xffffu);
        *(unsigned*)&Vh[vK][vN + 2]  = ((vv1.y & 0xffffu) << 16) | (vv1.x & 0xffffu);
        *(unsigned*)&Vh[vK][vN + 4]  = ((vv2.y & 0xffffu) << 16) | (vv2.x & 0xffffu);
        *(unsigned*)&Vl[vK][vN]      = (vv0.y & 0xffff0000u) | (vv0.x >> 16);
        *(unsigned*)&Vl[vK][vN + 2]  = (vv1.y & 0xffff0000u) | (vv1.x >> 16);
        *(unsigned*)&Vl[vK][vN + 4]  = (vv2.y & 0xffff0000u) | (vv2.x >> 16);
    };

    loadg(0); stores(); __syncthreads();

    for (int kt = 0; kt < 32; kt++) {
        if (kt + 1 < 32) loadg((kt + 1) << 4);

        unsigned ah[2][4], al[2][4], bh[3][2], bl_[3][2], t0, t1, t2, t3;
        ldsm4(ah[0], adAh);  ldsm4(ah[1], adAh + 768);
        ldsm4(al[0], adAl);  ldsm4(al[1], adAl + 768);
        ldsm4t(t0, t1, t2, t3, adVh);
        bh[0][0] = t0; bh[0][1] = t1; bh[1][0] = t2; bh[1][1] = t3;
        ldsm2t(t0, t1, adVh2);
        bh[2][0] = t0; bh[2][1] = t1;
        ldsm4t(t0, t1, t2, t3, adVl);
        bl_[0][0] = t0; bl_[0][1] = t1; bl_[1][0] = t2; bl_[1][1] = t3;
        ldsm2t(t0, t1, adVl2);
        bl_[2][0] = t0; bl_[2][1] = t1;

#pragma unroll
        for (int mf = 0; mf < 2; mf++)
#pragma unroll
            for (int nf = 0; nf < 3; nf++) {
                mma16(c[mf][nf], ah[mf], bh[nf][0], bh[nf][1]);
                mma16(c[mf][nf], ah[mf], bl_[nf][0], bl_[nf][1]);
                mma16(c[mf][nf], al[mf], bh[nf][0], bh[nf][1]);
            }

        __syncthreads();
        if (kt + 1 < 32) { stores(); __syncthreads(); }
    }

    const int b = bl >> 4, l = bl & 15;
#pragma unroll
    for (int mf = 0; mf < 2; mf++)
#pragma unroll
        for (int q2 = 0; q2 < 2; q2++) {
            const int n = n0 + wm * 32 + mf * 16 + gid + q2 * 8;
#pragma unroll
            for (int nf = 0; nf < 3; nf++) {
                const int d = wn * 24 + nf * 8 + tig * 2;
                unsigned* dst = g_O2 + ((size_t)(b * 512 + n)) * 1536 + l * 96 + d;
                *(uint2*)dst = make_uint2(psplit(c[mf][nf][q2 * 2 + 0]),
                                          psplit(c[mf][nf][q2 * 2 + 1]));
            }
        }
}

// ---------------------------------------------------------------------------
extern "C" void kernel_launch(void* const* d_in, const int* in_sizes, int n_in,
                              void* d_out, int out_size)
{
    const float* x     = (const float*)d_in[0];
    const float* ebias = (const float*)d_in[1];
    const float* eps   = (const float*)d_in[2];
    const float* Wq    = (const float*)d_in[3];
    const float* Wk    = (const float*)d_in[4];
    const float* Wv    = (const float*)d_in[5];
    const float* bv    = (const float*)d_in[6];
    const float* sigma = (const float*)d_in[7];
    const float* p     = (const float*)d_in[8];
    const float* Wout  = (const float*)d_in[9];
    float* out = (float*)d_out;

    unsigned *x2, *wq2, *wk2, *wv2, *wo2, *q2, *k2, *v2;
    cudaGetSymbolAddress((void**)&x2,  g_x2);
    cudaGetSymbolAddress((void**)&wq2, g_Wq2);
    cudaGetSymbolAddress((void**)&wk2, g_Wk2);
    cudaGetSymbolAddress((void**)&wv2, g_Wv2);
    cudaGetSymbolAddress((void**)&wo2, g_Wo2);
    cudaGetSymbolAddress((void**)&q2,  g_Q2);
    cudaGetSymbolAddress((void**)&k2,  g_K2);
    cudaGetSymbolAddress((void**)&v2,  g_V2);
    unsigned *o2;
    cudaGetSymbolAddress((void**)&o2, g_O2);

    // split inputs to bf16 hi/lo pairs
    split4<<<6144, 256>>>((const float4*)x, (uint4*)x2, 1572864);
    split4<<<576,  256>>>((const float4*)Wq, (uint4*)wq2, 147456);
    split4<<<576,  256>>>((const float4*)Wk, (uint4*)wk2, 147456);
    split4<<<1152, 256>>>((const float4*)Wv, (uint4*)wv2, 294912);
    split4<<<1152, 256>>>((const float4*)Wout, (uint4*)wo2, 294912);

    // projections
    gemm_bf<8,  false><<<dim3(12, 64), 256>>>(x2, wq2, nullptr, q2, 768, 768);
    gemm_bf<8,  false><<<dim3(12, 64), 256>>>(x2, wk2, nullptr, k2, 768, 768);
    gemm_bf<16, true ><<<dim3(24, 64), 256>>>(x2, wv2, bv, v2, 768, 1536);

    // scores + sigma^2*eps
    scores_bf<<<dim3(8, 8, Bb * Gg), 128>>>(eps, sigma);

    // mix + mish + softmax
    mix_softmax_kernel<<<Bb * Nn, 512>>>(ebias, p);

    // O = A @ V
    outv_bf<<<dim3(8, Bb * Ll), 256>>>();

    // output projection (fp32 store to d_out)
    gemm_bf<0, false><<<dim3(12, 64), 256>>>(o2, wo2, nullptr, out, 1536, 768);
}

// round 6
// speedup vs baseline: 2.5971x; 1.3281x over previous
#include <cuda_runtime.h>
#include <cuda_fp16.h>
#include <math.h>

#define Bb 16
#define Nn 512
#define Hh 768
#define Gg 8
#define Dd 96
#define Ll 16

// ---------------- scratch: separate fp16 hi/lo planes ----------------------
__device__ __half g_xh[(size_t)8192 * 768];
__device__ __half g_xl[(size_t)8192 * 768];
__device__ __half g_wqh[768 * 768];
__device__ __half g_wkh[768 * 768];
__device__ __half g_wvh[768 * 1536];
__device__ __half g_wvl[768 * 1536];
__device__ __half g_woh[1536 * 768];
__device__ __half g_wol[1536 * 768];
__device__ __half g_Qh[(size_t)128 * 512 * 96];
__device__ __half g_Ql[(size_t)128 * 512 * 96];
__device__ __half g_Kh[(size_t)128 * 512 * 96];
__device__ __half g_Kl[(size_t)128 * 512 * 96];
__device__ __half g_Vh[(size_t)256 * 512 * 96];
__device__ __half g_Vl[(size_t)256 * 512 * 96];
__device__ float  g_S [(size_t)128 * 512 * 512];
__device__ __half g_Ah[(size_t)256 * 512 * 512];
__device__ __half g_Oh[(size_t)8192 * 1536];
__device__ __half g_Ol[(size_t)8192 * 1536];

// ---------------- helpers --------------------------------------------------
__device__ __forceinline__ unsigned sptr(const void* p) {
    return (unsigned)__cvta_generic_to_shared(p);
}
__device__ __forceinline__ void cpa16(unsigned s, const void* g) {
    asm volatile("cp.async.cg.shared.global [%0], [%1], 16;" :: "r"(s), "l"(g));
}
__device__ __forceinline__ void cpcommit() {
    asm volatile("cp.async.commit_group;");
}
template<int W> __device__ __forceinline__ void cpwait() {
    asm volatile("cp.async.wait_group %0;" :: "n"(W));
}
__device__ __forceinline__ void ldsm4(unsigned f[4], unsigned a) {
    asm volatile("ldmatrix.sync.aligned.m8n8.x4.shared.b16 {%0,%1,%2,%3}, [%4];"
                 : "=r"(f[0]), "=r"(f[1]), "=r"(f[2]), "=r"(f[3]) : "r"(a));
}
__device__ __forceinline__ void ldsm4t(unsigned& r0, unsigned& r1, unsigned& r2,
                                       unsigned& r3, unsigned a) {
    asm volatile("ldmatrix.sync.aligned.m8n8.x4.trans.shared.b16 {%0,%1,%2,%3}, [%4];"
                 : "=r"(r0), "=r"(r1), "=r"(r2), "=r"(r3) : "r"(a));
}
__device__ __forceinline__ void ldsm2t(unsigned& r0, unsigned& r1, unsigned a) {
    asm volatile("ldmatrix.sync.aligned.m8n8.x2.trans.shared.b16 {%0,%1}, [%2];"
                 : "=r"(r0), "=r"(r1) : "r"(a));
}
__device__ __forceinline__ void mmaf16(float c[4], const unsigned a[4],
                                       unsigned b0, unsigned b1) {
    asm volatile(
        "mma.sync.aligned.m16n8k16.row.col.f32.f16.f16.f32 "
        "{%0,%1,%2,%3}, {%4,%5,%6,%7}, {%8,%9}, {%0,%1,%2,%3};"
        : "+f"(c[0]), "+f"(c[1]), "+f"(c[2]), "+f"(c[3])
        : "r"(a[0]), "r"(a[1]), "r"(a[2]), "r"(a[3]), "r"(b0), "r"(b1));
}
__device__ __forceinline__ void hsplit(float v, __half& h, __half& l) {
    h = __float2half_rn(v);
    l = __float2half_rn(v - __half2float(h));
}

// ---------------- split inputs ---------------------------------------------
__global__ void __launch_bounds__(256) split2k(const float4* __restrict__ in,
                                               __half* __restrict__ oh,
                                               __half* __restrict__ ol, int n4) {
    int i = blockIdx.x * 256 + threadIdx.x;
    if (i >= n4) return;
    float4 v = in[i];
    __half h0, h1, h2, h3, l0, l1, l2, l3;
    hsplit(v.x, h0, l0); hsplit(v.y, h1, l1);
    hsplit(v.z, h2, l2); hsplit(v.w, h3, l3);
    ((__half2*)oh)[i * 2]     = __halves2half2(h0, h1);
    ((__half2*)oh)[i * 2 + 1] = __halves2half2(h2, h3);
    ((__half2*)ol)[i * 2]     = __halves2half2(l0, l1);
    ((__half2*)ol)[i * 2 + 1] = __halves2half2(l2, l3);
}
__global__ void __launch_bounds__(256) split1k(const float4* __restrict__ in,
                                               __half* __restrict__ oh, int n4) {
    int i = blockIdx.x * 256 + threadIdx.x;
    if (i >= n4) return;
    float4 v = in[i];
    ((__half2*)oh)[i * 2]     = __halves2half2(__float2half_rn(v.x), __float2half_rn(v.y));
    ((__half2*)oh)[i * 2 + 1] = __halves2half2(__float2half_rn(v.z), __float2half_rn(v.w));
}

// ---------------------------------------------------------------------------
// Generic C = A[MxK] @ B[KxN]. BM=128 BN=128 BK=32, 3-stage cp.async, 256 thr.
// TERMS==1: hi planes only, 1 mma; TERMS==3: dual planes, 3 mma.
// HEADS>0: split-store permuted into [b][head][n][96]; F32OUT: fp32 rowmajor.
// ---------------------------------------------------------------------------
#define ASTR 10240          // 128 rows * 80B  (40-half padded rows)
#define BSTR 8704           // 32 rows * 272B  (136-half padded rows)

template<int TERMS, int HEADS, bool BIAS, bool F32OUT>
__global__ void __launch_bounds__(256) gemm16(
    const __half* __restrict__ Agh, const __half* __restrict__ Agl,
    const __half* __restrict__ Bgh, const __half* __restrict__ Bgl,
    const float* __restrict__ bias,
    __half* __restrict__ outH, __half* __restrict__ outL,
    float* __restrict__ outF, int K, int N)
{
    extern __shared__ char smem[];
    char* p = smem;
    __half* sAh = (__half*)p; p += 3 * ASTR;
    __half* sAl = nullptr;
    if (TERMS == 3) { sAl = (__half*)p; p += 3 * ASTR; }
    __half* sBh = (__half*)p; p += 3 * BSTR;
    __half* sBl = nullptr;
    if (TERMS == 3) { sBl = (__half*)p; }

    const int tid = threadIdx.x;
    const int lane = tid & 31, warp = tid >> 5;
    const int wm = warp >> 2, wn = warp & 3;
    const int gid = lane >> 2, tig = lane & 3;
    const int m0 = blockIdx.y * 128, n0 = blockIdx.x * 128;

    const int aR = tid >> 1, aC = (tid & 1) * 16;
    const int bR = tid >> 3, bC = (tid & 7) * 16;

    const unsigned sAhb = sptr(sAh), sBhb = sptr(sBh);
    const unsigned sAlb = TERMS == 3 ? sptr(sAl) : 0;
    const unsigned sBlb = TERMS == 3 ? sptr(sBl) : 0;

    auto issue = [&](int kt, int s) {
        const int k0 = kt << 5;
        const __half* ga = Agh + (size_t)(m0 + aR) * K + k0 + aC;
        unsigned sa = sAhb + s * ASTR + aR * 80 + aC * 2;
        cpa16(sa, ga); cpa16(sa + 16, ga + 8);
        const __half* gb = Bgh + (size_t)(k0 + bR) * N + n0 + bC;
        unsigned sb = sBhb + s * BSTR + bR * 272 + bC * 2;
        cpa16(sb, gb); cpa16(sb + 16, gb + 8);
        if (TERMS == 3) {
            const __half* ga2 = Agl + (size_t)(m0 + aR) * K + k0 + aC;
            unsigned sa2 = sAlb + s * ASTR + aR * 80 + aC * 2;
            cpa16(sa2, ga2); cpa16(sa2 + 16, ga2 + 8);
            const __half* gb2 = Bgl + (size_t)(k0 + bR) * N + n0 + bC;
            unsigned sb2 = sBlb + s * BSTR + bR * 272 + bC * 2;
            cpa16(sb2, gb2); cpa16(sb2 + 16, gb2 + 8);
        }
        cpcommit();
    };

    float c[4][4][4];
#pragma unroll
    for (int i = 0; i < 4; i++)
#pragma unroll
        for (int j = 0; j < 4; j++)
#pragma unroll
            for (int q = 0; q < 4; q++) c[i][j][q] = 0.f;

    const unsigned aOff = (wm * 64 + (lane & 15)) * 80 + (lane >> 4) * 16;
    const unsigned bOff = (lane & 15) * 272 + (wn * 32 + (lane >> 4) * 8) * 2;

    issue(0, 0); issue(1, 1);
    const int KT = K >> 5;

    for (int kt = 0; kt < KT; kt++) {
        cpwait<1>();
        __syncthreads();
        const int s = kt % 3;
        const unsigned aB = sAhb + s * ASTR + aOff;
        const unsigned bB = sBhb + s * BSTR + bOff;
        const unsigned aB2 = TERMS == 3 ? sAlb + s * ASTR + aOff : 0;
        const unsigned bB2 = TERMS == 3 ? sBlb + s * BSTR + bOff : 0;

#pragma unroll
        for (int k16 = 0; k16 < 2; k16++) {
            unsigned ah[4][4], al[4][4], bh[4][2], bl[4][2], t0, t1, t2, t3;
#pragma unroll
            for (int mf = 0; mf < 4; mf++) {
                ldsm4(ah[mf], aB + mf * 1280 + k16 * 32);
                if (TERMS == 3) ldsm4(al[mf], aB2 + mf * 1280 + k16 * 32);
            }
#pragma unroll
            for (int nf2 = 0; nf2 < 2; nf2++) {
                ldsm4t(t0, t1, t2, t3, bB + k16 * 4352 + nf2 * 32);
                bh[nf2 * 2][0] = t0; bh[nf2 * 2][1] = t1;
                bh[nf2 * 2 + 1][0] = t2; bh[nf2 * 2 + 1][1] = t3;
                if (TERMS == 3) {
                    ldsm4t(t0, t1, t2, t3, bB2 + k16 * 4352 + nf2 * 32);
                    bl[nf2 * 2][0] = t0; bl[nf2 * 2][1] = t1;
                    bl[nf2 * 2 + 1][0] = t2; bl[nf2 * 2 + 1][1] = t3;
                }
            }
#pragma unroll
            for (int mf = 0; mf < 4; mf++)
#pragma unroll
                for (int nf = 0; nf < 4; nf++) {
                    mmaf16(c[mf][nf], ah[mf], bh[nf][0], bh[nf][1]);
                    if (TERMS == 3) {
                        mmaf16(c[mf][nf], ah[mf], bl[nf][0], bl[nf][1]);
                        mmaf16(c[mf][nf], al[mf], bh[nf][0], bh[nf][1]);
                    }
                }
        }
        const int kn = kt + 2;
        if (kn < KT) issue(kn, kn % 3); else cpcommit();
    }

#pragma unroll
    for (int mf = 0; mf < 4; mf++)
#pragma unroll
        for (int q2 = 0; q2 < 2; q2++) {
            const int row = m0 + wm * 64 + mf * 16 + gid + q2 * 8;
            const int b = row >> 9, n = row & 511;
#pragma unroll
            for (int nf = 0; nf < 4; nf++) {
                const int col = n0 + wn * 32 + nf * 8 + tig * 2;
                float v0 = c[mf][nf][q2 * 2 + 0];
                float v1 = c[mf][nf][q2 * 2 + 1];
                if (BIAS) { v0 += bias[col]; v1 += bias[col + 1]; }
                if (F32OUT) {
                    *(float2*)(outF + (size_t)row * N + col) = make_float2(v0, v1);
                } else {
                    const int h = col / 96, d = col - h * 96;
                    const size_t idx = (((size_t)(b * HEADS + h)) * 512 + n) * 96 + d;
                    __half h0, h1, l0, l1;
                    hsplit(v0, h0, l0); hsplit(v1, h1, l1);
                    *(__half2*)(outH + idx) = __halves2half2(h0, h1);
                    *(__half2*)(outL + idx) = __halves2half2(l0, l1);
                }
            }
        }
}

// ---------------------------------------------------------------------------
// Scores: S[bg,n,m] = Q.K^T + sigma^2*eps.  Both operands [row][96] K-major,
// 3-term fp16 split.  BM=BN=128, BK=32, KT=3, 3 stages.
// ---------------------------------------------------------------------------
__global__ void __launch_bounds__(256) scores16(
    const float* __restrict__ eps, const float* __restrict__ sigma)
{
    extern __shared__ char smem[];
    char* p = smem;
    __half* sQh = (__half*)p; p += 3 * ASTR;
    __half* sQl = (__half*)p; p += 3 * ASTR;
    __half* sKh = (__half*)p; p += 3 * ASTR;
    __half* sKl = (__half*)p;

    const int tid = threadIdx.x;
    const int lane = tid & 31, warp = tid >> 5;
    const int wm = warp >> 2, wn = warp & 3;
    const int gid = lane >> 2, tig = lane & 3;
    const int bg = blockIdx.z;
    const int sn0 = blockIdx.y * 128, sm0 = blockIdx.x * 128;

    const __half* Qhp = g_Qh + (size_t)bg * Nn * Dd;
    const __half* Qlp = g_Ql + (size_t)bg * Nn * Dd;
    const __half* Khp = g_Kh + (size_t)bg * Nn * Dd;
    const __half* Klp = g_Kl + (size_t)bg * Nn * Dd;

    const int aR = tid >> 1, aC = (tid & 1) * 16;
    const unsigned bQh = sptr(sQh), bQl = sptr(sQl);
    const unsigned bKh = sptr(sKh), bKl = sptr(sKl);

    auto issue = [&](int kt, int s) {
        const int k0 = kt << 5;
        unsigned so = s * ASTR + aR * 80 + aC * 2;
        size_t go = (size_t)aR * 96 + k0 + aC;
        cpa16(bQh + so, Qhp + (size_t)sn0 * 96 + go);
        cpa16(bQh + so + 16, Qhp + (size_t)sn0 * 96 + go + 8);
        cpa16(bQl + so, Qlp + (size_t)sn0 * 96 + go);
        cpa16(bQl + so + 16, Qlp + (size_t)sn0 * 96 + go + 8);
        cpa16(bKh + so, Khp + (size_t)sm0 * 96 + go);
        cpa16(bKh + so + 16, Khp + (size_t)sm0 * 96 + go + 8);
        cpa16(bKl + so, Klp + (size_t)sm0 * 96 + go);
        cpa16(bKl + so + 16, Klp + (size_t)sm0 * 96 + go + 8);
        cpcommit();
    };

    float c[4][4][4];
#pragma unroll
    for (int i = 0; i < 4; i++)
#pragma unroll
        for (int j = 0; j < 4; j++)
#pragma unroll
            for (int q = 0; q < 4; q++) c[i][j][q] = 0.f;

    const unsigned aOff = (wm * 64 + (lane & 15)) * 80 + (lane >> 4) * 16;
    const unsigned kOff = (wn * 32 + (lane & 15)) * 80 + (lane >> 4) * 16;

    issue(0, 0); issue(1, 1);

    for (int kt = 0; kt < 3; kt++) {
        cpwait<1>();
        __syncthreads();
        const int s = kt;
        const unsigned aH = bQh + s * ASTR + aOff, aL = bQl + s * ASTR + aOff;
        const unsigned kH = bKh + s * ASTR + kOff, kL = bKl + s * ASTR + kOff;

#pragma unroll
        for (int k16 = 0; k16 < 2; k16++) {
            unsigned ah[4][4], al[4][4], f[4], bh[4][2], bl[4][2];
#pragma unroll
            for (int mf = 0; mf < 4; mf++) {
                ldsm4(ah[mf], aH + mf * 1280 + k16 * 32);
                ldsm4(al[mf], aL + mf * 1280 + k16 * 32);
            }
#pragma unroll
            for (int nf2 = 0; nf2 < 2; nf2++) {
                ldsm4(f, kH + nf2 * 1280 + k16 * 32);
                bh[nf2 * 2][0] = f[0]; bh[nf2 * 2][1] = f[2];
                bh[nf2 * 2 + 1][0] = f[1]; bh[nf2 * 2 + 1][1] = f[3];
                ldsm4(f, kL + nf2 * 1280 + k16 * 32);
                bl[nf2 * 2][0] = f[0]; bl[nf2 * 2][1] = f[2];
                bl[nf2 * 2 + 1][0] = f[1]; bl[nf2 * 2 + 1][1] = f[3];
            }
#pragma unroll
            for (int mf = 0; mf < 4; mf++)
#pragma unroll
                for (int nf = 0; nf < 4; nf++) {
                    mmaf16(c[mf][nf], ah[mf], bh[nf][0], bh[nf][1]);
                    mmaf16(c[mf][nf], ah[mf], bl[nf][0], bl[nf][1]);
                    mmaf16(c[mf][nf], al[mf], bh[nf][0], bh[nf][1]);
                }
        }
        const int kn = kt + 2;
        if (kn < 3) issue(kn, kn); else cpcommit();
    }

    float s2 = sigma[bg & 7];
    s2 = s2 * s2;
#pragma unroll
    for (int mf = 0; mf < 4; mf++)
#pragma unroll
        for (int q2 = 0; q2 < 2; q2++) {
            const int n = sn0 + wm * 64 + mf * 16 + gid + q2 * 8;
#pragma unroll
            for (int nf = 0; nf < 4; nf++) {
                const int m = sm0 + wn * 32 + nf * 8 + tig * 2;
                const size_t idx = ((size_t)bg * Nn + n) * Nn + m;
                float2 ev = *(const float2*)(eps + idx);
                *(float2*)(g_S + idx) = make_float2(
                    c[mf][nf][q2 * 2 + 0] + s2 * ev.x,
                    c[mf][nf][q2 * 2 + 1] + s2 * ev.y);
            }
        }
}

// ---------------------------------------------------------------------------
// Mix + mish + softmax.  A written as single fp16.
// ---------------------------------------------------------------------------
__global__ void __launch_bounds__(512) mix_softmax_kernel(
    const float* __restrict__ encoding_bias, const float* __restrict__ p)
{
    int bn = blockIdx.x;
    int b = bn >> 9, n = bn & 511;
    int tid = threadIdx.x;
    int lane = tid & 31, warp = tid >> 5;

    __shared__ float ps[128];
    __shared__ float red[16][17];
    __shared__ float rmax[16];
    __shared__ float rsum[16];

    if (tid < 128) ps[tid] = p[tid];
    __syncthreads();

    float s[8];
#pragma unroll
    for (int g = 0; g < 8; g++)
        s[g] = g_S[(((size_t)(b * 8 + g)) * 512 + n) * 512 + tid];
    float bias = encoding_bias[((size_t)bn) * 512 + tid];
    const float scale = 0.03608439182435161f;

    float vals[16];
#pragma unroll
    for (int l = 0; l < 16; l++) {
        float t = 0.f;
#pragma unroll
        for (int g = 0; g < 8; g++) t = fmaf(s[g], ps[g * 16 + l], t);
        float e = __expf(fminf(t, 15.f));
        float num = e * (e + 2.f);
        float mish = t * (num / (num + 2.f));
        vals[l] = mish * scale + bias;
    }

#pragma unroll
    for (int l = 0; l < 16; l++) {
        float v = vals[l];
#pragma unroll
        for (int o = 16; o > 0; o >>= 1)
            v = fmaxf(v, __shfl_xor_sync(0xffffffffu, v, o));
        if (lane == 0) red[l][warp] = v;
    }
    __syncthreads();
    {
        float v = (lane < 16) ? red[warp][lane] : -3.0e38f;
#pragma unroll
        for (int o = 8; o > 0; o >>= 1)
            v = fmaxf(v, __shfl_xor_sync(0xffffffffu, v, o));
        if (lane == 0) rmax[warp] = v;
    }
    __syncthreads();

#pragma unroll
    for (int l = 0; l < 16; l++) {
        vals[l] = __expf(vals[l] - rmax[l]);
        float v = vals[l];
#pragma unroll
        for (int o = 16; o > 0; o >>= 1)
            v += __shfl_xor_sync(0xffffffffu, v, o);
        if (lane == 0) red[l][warp] = v;
    }
    __syncthreads();
    {
        float v = (lane < 16) ? red[warp][lane] : 0.f;
#pragma unroll
        for (int o = 8; o > 0; o >>= 1)
            v += __shfl_xor_sync(0xffffffffu, v, o);
        if (lane == 0) rsum[warp] = v;
    }
    __syncthreads();

#pragma unroll
    for (int l = 0; l < 16; l++)
        g_Ah[(((size_t)(b * 16 + l)) * 512 + n) * 512 + tid] =
            __float2half_rn(vals[l] / rsum[l]);
}

// ---------------------------------------------------------------------------
// O = A @ V per (b,l).  A single fp16 [bl][n][m], V dual [bl][m][d].
// BM=128, BN=96, BK=32, KT=16, 2-term.  Warp tile 64x24.
// ---------------------------------------------------------------------------
#define VSTR 6656          // 32 rows * 208B (104-half padded rows)

__global__ void __launch_bounds__(256) outv16()
{
    extern __shared__ char smem[];
    char* p = smem;
    __half* sA = (__half*)p;  p += 3 * ASTR;
    __half* sVh = (__half*)p; p += 3 * VSTR;
    __half* sVl = (__half*)p;

    const int tid = threadIdx.x;
    const int lane = tid & 31, warp = tid >> 5;
    const int wm = warp >> 2, wn = warp & 3;
    const int gid = lane >> 2, tig = lane & 3;
    const int bl = blockIdx.y;
    const int n0 = blockIdx.x * 128;

    const __half* Ap = g_Ah + (size_t)bl * Nn * Nn;
    const __half* Vhp = g_Vh + (size_t)bl * Nn * Dd;
    const __half* Vlp = g_Vl + (size_t)bl * Nn * Dd;

    const int aR = tid >> 1, aC = (tid & 1) * 16;
    const int vR = tid / 6, vC = (tid % 6) * 16;
    const bool vAct = tid < 192;

    const unsigned bA = sptr(sA), bVh = sptr(sVh), bVl = sptr(sVl);

    auto issue = [&](int kt, int s) {
        const int k0 = kt << 5;
        unsigned sa = bA + s * ASTR + aR * 80 + aC * 2;
        const __half* ga = Ap + (size_t)(n0 + aR) * 512 + k0 + aC;
        cpa16(sa, ga); cpa16(sa + 16, ga + 8);
        if (vAct) {
            unsigned sv = s * VSTR + vR * 208 + vC * 2;
            const __half* gv = Vhp + (size_t)(k0 + vR) * 96 + vC;
            cpa16(bVh + sv, gv); cpa16(bVh + sv + 16, gv + 8);
            const __half* gv2 = Vlp + (size_t)(k0 + vR) * 96 + vC;
            cpa16(bVl + sv, gv2); cpa16(bVl + sv + 16, gv2 + 8);
        }
        cpcommit();
    };

    float c[4][3][4];
#pragma unroll
    for (int i = 0; i < 4; i++)
#pragma unroll
        for (int j = 0; j < 3; j++)
#pragma unroll
            for (int q = 0; q < 4; q++) c[i][j][q] = 0.f;

    const unsigned aOff = (wm * 64 + (lane & 15)) * 80 + (lane >> 4) * 16;
    const unsigned vOff = (lane & 15) * 208 + (wn * 24 + (lane >> 4) * 8) * 2;
    const unsigned vOff2 = (lane & 15) * 208 + (wn * 24 + 16) * 2;

    issue(0, 0); issue(1, 1);

    for (int kt = 0; kt < 16; kt++) {
        cpwait<1>();
        __syncthreads();
        const int s = kt % 3;
        const unsigned aB = bA + s * ASTR + aOff;
        const unsigned vH = bVh + s * VSTR, vL = bVl + s * VSTR;

#pragma unroll
        for (int k16 = 0; k16 < 2; k16++) {
            unsigned ah[4][4], bh[3][2], blr[3][2], t0, t1, t2, t3;
#pragma unroll
            for (int mf = 0; mf < 4; mf++)
                ldsm4(ah[mf], aB + mf * 1280 + k16 * 32);
            ldsm4t(t0, t1, t2, t3, vH + vOff + k16 * 3328);
            bh[0][0] = t0; bh[0][1] = t1; bh[1][0] = t2; bh[1][1] = t3;
            ldsm2t(t0, t1, vH + vOff2 + k16 * 3328);
            bh[2][0] = t0; bh[2][1] = t1;
            ldsm4t(t0, t1, t2, t3, vL + vOff + k16 * 3328);
            blr[0][0] = t0; blr[0][1] = t1; blr[1][0] = t2; blr[1][1] = t3;
            ldsm2t(t0, t1, vL + vOff2 + k16 * 3328);
            blr[2][0] = t0; blr[2][1] = t1;

#pragma unroll
            for (int mf = 0; mf < 4; mf++)
#pragma unroll
                for (int nf = 0; nf < 3; nf++) {
                    mmaf16(c[mf][nf], ah[mf], bh[nf][0], bh[nf][1]);
                    mmaf16(c[mf][nf], ah[mf], blr[nf][0], blr[nf][1]);
                }
        }
        const int kn = kt + 2;
        if (kn < 16) issue(kn, kn % 3); else cpcommit();
    }

    const int b = bl >> 4, l = bl & 15;
#pragma unroll
    for (int mf = 0; mf < 4; mf++)
#pragma unroll
        for (int q2 = 0; q2 < 2; q2++) {
            const int n = n0 + wm * 64 + mf * 16 + gid + q2 * 8;
#pragma unroll
            for (int nf = 0; nf < 3; nf++) {
                const int d = wn * 24 + nf * 8 + tig * 2;
                const size_t idx = ((size_t)(b * 512 + n)) * 1536 + l * 96 + d;
                __half h0, h1, l0, l1;
                hsplit(c[mf][nf][q2 * 2 + 0], h0, l0);
                hsplit(c[mf][nf][q2 * 2 + 1], h1, l1);
                *(__half2*)(g_Oh + idx) = __halves2half2(h0, h1);
                *(__half2*)(g_Ol + idx) = __halves2half2(l0, l1);
            }
        }
}

// ---------------------------------------------------------------------------
extern "C" void kernel_launch(void* const* d_in, const int* in_sizes, int n_in,
                              void* d_out, int out_size)
{
    const float* x     = (const float*)d_in[0];
    const float* ebias = (const float*)d_in[1];
    const float* eps   = (const float*)d_in[2];
    const float* Wq    = (const float*)d_in[3];
    const float* Wk    = (const float*)d_in[4];
    const float* Wv    = (const float*)d_in[5];
    const float* bv    = (const float*)d_in[6];
    const float* sigma = (const float*)d_in[7];
    const float* p     = (const float*)d_in[8];
    const float* Wout  = (const float*)d_in[9];
    float* out = (float*)d_out;

    __half *xh, *xl, *wqh, *wkh, *wvh, *wvl, *woh, *wol;
    __half *qh, *ql, *kh, *kl, *vh, *vl, *oh, *ol;
    cudaGetSymbolAddress((void**)&xh,  g_xh);
    cudaGetSymbolAddress((void**)&xl,  g_xl);
    cudaGetSymbolAddress((void**)&wqh, g_wqh);
    cudaGetSymbolAddress((void**)&wkh, g_wkh);
    cudaGetSymbolAddress((void**)&wvh, g_wvh);
    cudaGetSymbolAddress((void**)&wvl, g_wvl);
    cudaGetSymbolAddress((void**)&woh, g_woh);
    cudaGetSymbolAddress((void**)&wol, g_wol);
    cudaGetSymbolAddress((void**)&qh,  g_Qh);
    cudaGetSymbolAddress((void**)&ql,  g_Ql);
    cudaGetSymbolAddress((void**)&kh,  g_Kh);
    cudaGetSymbolAddress((void**)&kl,  g_Kl);
    cudaGetSymbolAddress((void**)&vh,  g_Vh);
    cudaGetSymbolAddress((void**)&vl,  g_Vl);
    cudaGetSymbolAddress((void**)&oh,  g_Oh);
    cudaGetSymbolAddress((void**)&ol,  g_Ol);

    const int SM1 = 3 * ASTR + 3 * BSTR;                 // 56832
    const int SM3 = 6 * ASTR + 6 * BSTR;                 // 113664
    const int SMS = 12 * ASTR;                           // 122880
    const int SMO = 3 * ASTR + 6 * VSTR;                 // 70656

    cudaFuncSetAttribute(gemm16<1, 8,  false, false>,
        cudaFuncAttributeMaxDynamicSharedMemorySize, SM1);
    cudaFuncSetAttribute(gemm16<3, 16, true,  false>,
        cudaFuncAttributeMaxDynamicSharedMemorySize, SM3);
    cudaFuncSetAttribute(gemm16<3, 0,  false, true>,
        cudaFuncAttributeMaxDynamicSharedMemorySize, SM3);
    cudaFuncSetAttribute(scores16,
        cudaFuncAttributeMaxDynamicSharedMemorySize, SMS);
    cudaFuncSetAttribute(outv16,
        cudaFuncAttributeMaxDynamicSharedMemorySize, SMO);

    // splits
    split2k<<<6144, 256>>>((const float4*)x, xh, xl, 1572864);
    split1k<<<576,  256>>>((const float4*)Wq, wqh, 147456);
    split1k<<<576,  256>>>((const float4*)Wk, wkh, 147456);
    split2k<<<1152, 256>>>((const float4*)Wv, wvh, wvl, 294912);
    split2k<<<1152, 256>>>((const float4*)Wout, woh, wol, 294912);

    // Q/K projections: single-plane fp16, split-stored outputs
    gemm16<1, 8, false, false><<<dim3(6, 64), 256, SM1>>>(
        xh, nullptr, wqh, nullptr, nullptr, qh, ql, nullptr, 768, 768);
    gemm16<1, 8, false, false><<<dim3(6, 64), 256, SM1>>>(
        xh, nullptr, wkh, nullptr, nullptr, kh, kl, nullptr, 768, 768);
    // V projection: 3-term
    gemm16<3, 16, true, false><<<dim3(12, 64), 256, SM3>>>(
        xh, xl, wvh, wvl, bv, vh, vl, nullptr, 768, 1536);

    // scores + sigma^2*eps (3-term on split Q/K)
    scores16<<<dim3(4, 4, 128), 256, SMS>>>(eps, sigma);

    // mix + mish + softmax -> A (fp16)
    mix_softmax_kernel<<<Bb * Nn, 512>>>(ebias, p);

    // O = A @ V (2-term)
    outv16<<<dim3(4, 256), 256, SMO>>>();

    // output projection: 3-term, fp32 out
    gemm16<3, 0, false, true><<<dim3(6, 64), 256, SM3>>>(
        oh, ol, woh, wol, nullptr, nullptr, nullptr, out, 1536, 768);
}